// round 2
// baseline (speedup 1.0000x reference)
#include <cuda_runtime.h>
#include <cstdint>

// Problem: out = X (4096x4096) @ W^T, W[4y+r, 4x+c] = eigens[y,x,(r-c)&3]
// Strategy: expand W from eigens (pre-rounded to tf32), pre-round X to tf32,
//           then tiled tf32 mma.sync GEMM with fp32 accumulation.

#define B_DIM 4096
#define N_DIM 4096
#define K_DIM 4096

// Scratch (device globals: allocation-free per harness rules)
__device__ float g_W[(size_t)N_DIM * K_DIM];  // 64 MB, [o][i] K-major
__device__ float g_X[(size_t)B_DIM * K_DIM];  // 64 MB, tf32-rounded copy of x

__device__ __forceinline__ uint32_t tf32r(float f) {
    uint32_t u;
    asm("cvt.rna.tf32.f32 %0, %1;" : "=r"(u) : "f"(f));
    return u;
}

// ---------------------------------------------------------------------------
// Expansion: W[4y+r][4x+c] = tf32(eigens[y][x][(r-c)&3]); one thread = 4 elems
// ---------------------------------------------------------------------------
__global__ void expand_w_kernel(const float* __restrict__ eig) {
    int t = blockIdx.x * blockDim.x + threadIdx.x;   // over 4096 * 1024
    if (t >= N_DIM * (K_DIM / 4)) return;
    int x = t & 1023;        // gx index
    int o = t >> 10;         // output row, 0..4095
    int y = o >> 2;
    int r = o & 3;
    const float4 e = reinterpret_cast<const float4*>(eig)[y * 1024 + x];
    // component c gets e[(r-c)&3]
    float4 wv;
    switch (r) {
        case 0:  wv = make_float4(e.x, e.w, e.z, e.y); break;
        case 1:  wv = make_float4(e.y, e.x, e.w, e.z); break;
        case 2:  wv = make_float4(e.z, e.y, e.x, e.w); break;
        default: wv = make_float4(e.w, e.z, e.y, e.x); break;
    }
    uint4 u;
    u.x = tf32r(wv.x); u.y = tf32r(wv.y); u.z = tf32r(wv.z); u.w = tf32r(wv.w);
    reinterpret_cast<uint4*>(g_W)[(size_t)o * 1024 + x] = u;
}

__global__ void round_x_kernel(const float* __restrict__ xin) {
    int t = blockIdx.x * blockDim.x + threadIdx.x;   // over 4096*4096/4
    if (t >= B_DIM * (K_DIM / 4)) return;
    const float4 v = reinterpret_cast<const float4*>(xin)[t];
    uint4 u;
    u.x = tf32r(v.x); u.y = tf32r(v.y); u.z = tf32r(v.z); u.w = tf32r(v.w);
    reinterpret_cast<uint4*>(g_X)[t] = u;
}

// ---------------------------------------------------------------------------
// GEMM: out[b][o] = sum_k g_X[b][k] * g_W[o][k]
// Block tile 128x128x32, 256 threads (8 warps, 4x2), warp tile 32x64.
// mma.sync.m16n8k8 tf32, cp.async double-buffered smem, stride 36 (pad 4).
// ---------------------------------------------------------------------------
#define BM 128
#define BN 128
#define BK 32
#define LDSW 36                       // smem row stride in words (conflict-free)
#define STAGE_F (2 * 128 * LDSW)      // floats per stage (A tile + B tile) = 9216
#define SMEM_BYTES (2 * STAGE_F * 4)  // 73728

__global__ void __launch_bounds__(256) gemm_tf32_kernel(float* __restrict__ out) {
    extern __shared__ float smem[];

    const int tid  = threadIdx.x;
    const int bm0  = blockIdx.y * BM;
    const int bn0  = blockIdx.x * BN;

    const int warp  = tid >> 5;
    const int lane  = tid & 31;
    const int g     = lane >> 2;   // group id 0..7
    const int tg    = lane & 3;    // thread-in-group 0..3
    const int warpM = warp & 3;    // 0..3
    const int warpN = warp >> 2;   // 0..1
    const int m0    = warpM * 32;
    const int n0    = warpN * 64;

    // per-thread gmem->smem copy coordinates (8 x 16B per k-tile)
    const int lrow = 0; (void)lrow;

    float acc[2][8][4];
    #pragma unroll
    for (int mi = 0; mi < 2; mi++)
        #pragma unroll
        for (int ni = 0; ni < 8; ni++)
            #pragma unroll
            for (int q = 0; q < 4; q++) acc[mi][ni][q] = 0.0f;

    auto load_tile = [&](int kk, int buf) {
        float* base  = smem + buf * STAGE_F;
        float* baseB = base + BM * LDSW;
        #pragma unroll
        for (int j = 0; j < 4; j++) {
            int l   = tid + j * 256;
            int row = l >> 3;
            int c4  = l & 7;
            const float* src = g_X + (size_t)(bm0 + row) * K_DIM + kk + c4 * 4;
            uint32_t dst = (uint32_t)__cvta_generic_to_shared(base + row * LDSW + c4 * 4);
            asm volatile("cp.async.cg.shared.global [%0], [%1], 16;\n"
                         :: "r"(dst), "l"(src) : "memory");
        }
        #pragma unroll
        for (int j = 0; j < 4; j++) {
            int l   = tid + j * 256;
            int row = l >> 3;
            int c4  = l & 7;
            const float* src = g_W + (size_t)(bn0 + row) * K_DIM + kk + c4 * 4;
            uint32_t dst = (uint32_t)__cvta_generic_to_shared(baseB + row * LDSW + c4 * 4);
            asm volatile("cp.async.cg.shared.global [%0], [%1], 16;\n"
                         :: "r"(dst), "l"(src) : "memory");
        }
        asm volatile("cp.async.commit_group;\n" ::: "memory");
    };

    const int NK = K_DIM / BK;   // 128
    load_tile(0, 0);

    for (int kt = 0; kt < NK; kt++) {
        if (kt + 1 < NK) {
            load_tile((kt + 1) * BK, (kt + 1) & 1);
            asm volatile("cp.async.wait_group 1;\n" ::: "memory");
        } else {
            asm volatile("cp.async.wait_group 0;\n" ::: "memory");
        }
        __syncthreads();

        const float* base = smem + (kt & 1) * STAGE_F;
        const uint32_t* Asu = reinterpret_cast<const uint32_t*>(base);
        const uint32_t* Bsu = reinterpret_cast<const uint32_t*>(base + BM * LDSW);

        #pragma unroll
        for (int ks = 0; ks < 4; ks++) {
            const int kb = ks * 8;
            uint32_t af[2][4];
            #pragma unroll
            for (int mi = 0; mi < 2; mi++) {
                int rbase = (m0 + mi * 16 + g) * LDSW + kb + tg;
                af[mi][0] = Asu[rbase];
                af[mi][1] = Asu[rbase + 8 * LDSW];
                af[mi][2] = Asu[rbase + 4];
                af[mi][3] = Asu[rbase + 8 * LDSW + 4];
            }
            #pragma unroll
            for (int ni = 0; ni < 8; ni++) {
                int rb = (n0 + ni * 8 + g) * LDSW + kb + tg;
                uint32_t b0 = Bsu[rb];
                uint32_t b1 = Bsu[rb + 4];
                #pragma unroll
                for (int mi = 0; mi < 2; mi++) {
                    asm volatile(
                        "mma.sync.aligned.m16n8k8.row.col.f32.tf32.tf32.f32 "
                        "{%0,%1,%2,%3}, {%4,%5,%6,%7}, {%8,%9}, {%0,%1,%2,%3};\n"
                        : "+f"(acc[mi][ni][0]), "+f"(acc[mi][ni][1]),
                          "+f"(acc[mi][ni][2]), "+f"(acc[mi][ni][3])
                        : "r"(af[mi][0]), "r"(af[mi][1]), "r"(af[mi][2]), "r"(af[mi][3]),
                          "r"(b0), "r"(b1));
                }
            }
        }
        __syncthreads();
    }

    // Epilogue: d0,d1 -> (row g, cols 2tg,2tg+1); d2,d3 -> row g+8
    #pragma unroll
    for (int mi = 0; mi < 2; mi++) {
        #pragma unroll
        for (int ni = 0; ni < 8; ni++) {
            int row = bm0 + m0 + mi * 16 + g;
            int col = bn0 + n0 + ni * 8 + 2 * tg;
            *reinterpret_cast<float2*>(out + (size_t)row * N_DIM + col) =
                make_float2(acc[mi][ni][0], acc[mi][ni][1]);
            *reinterpret_cast<float2*>(out + (size_t)(row + 8) * N_DIM + col) =
                make_float2(acc[mi][ni][2], acc[mi][ni][3]);
        }
    }
}

// ---------------------------------------------------------------------------
extern "C" void kernel_launch(void* const* d_in, const int* in_sizes, int n_in,
                              void* d_out, int out_size) {
    const float* x   = (const float*)d_in[0];   // (4096, 4096) f32
    const float* eig = (const float*)d_in[1];   // (1024, 1024, 4) f32
    float* out       = (float*)d_out;           // (4096, 4096) f32

    // allow 72 KB dynamic smem for the GEMM
    static bool attr_set = false;
    cudaFuncSetAttribute(gemm_tf32_kernel,
                         cudaFuncAttributeMaxDynamicSharedMemorySize, SMEM_BYTES);

    round_x_kernel<<<(B_DIM * K_DIM / 4 + 255) / 256, 256>>>(x);
    expand_w_kernel<<<(N_DIM * K_DIM / 4 + 255) / 256, 256>>>(eig);

    dim3 grid(N_DIM / BN, B_DIM / BM);
    gemm_tf32_kernel<<<grid, 256, SMEM_BYTES>>>(out);
    (void)attr_set; (void)in_sizes; (void)n_in; (void)out_size;
}

// round 4
// speedup vs baseline: 1.7406x; 1.7406x over previous
#include <cuda_runtime.h>
#include <cstdint>

// Block-circulant linear via length-4 DFT diagonalization:
//   out[b,4y+r] = irfft4( sum_x rfft4(eigens[y,x]) * rfft4(xblk[b,x]) )[r]
// Frequency components (real arithmetic):
//   u0 = a+b+c+d, u1r = a-c, u1i = d-b, u2 = a-b+c-d       (per x block)
//   Planes (scale folded in): P0=Fe0/4, P2=Fe2/4, P1r=(e0-e2)/2,
//                             P1i=(e3-e1)/2, P1n=-(e3-e1)/2
//   F0  = sum P0*u0 ; F2 = sum P2*u2
//   F1r = sum P1r*u1r + P1n*u1i ; F1i = sum P1i*u1r + P1r*u1i
//   o0=F0+F1r+F2  o1=F0-F1i-F2  o2=F0-F1r+F2  o3=F0+F1i-F2
// => 6/16 of the dense GEMM work, fused butterfly epilogue.

#define B_DIM 4096
#define GX 1024
#define GY 1024
#define N_DIM 4096

// Scratch
__device__ float g_U[(size_t)B_DIM * 4096];        // [b][comp*1024 + x], 64 MB
__device__ float g_E[(size_t)5 * GY * GX];         // [plane][y][x], 20 MB

__device__ __forceinline__ uint32_t tf32r(float f) {
    uint32_t u;
    asm("cvt.rna.tf32.f32 %0, %1;" : "=r"(u) : "f"(f));
    return u;
}

// ---------------------------------------------------------------------------
// transform_x: one thread per (b, xblk)
// ---------------------------------------------------------------------------
__global__ void transform_x_kernel(const float* __restrict__ xin) {
    int t = blockIdx.x * blockDim.x + threadIdx.x;   // 4096*1024
    if (t >= B_DIM * GX) return;
    int b = t >> 10;
    int x = t & 1023;
    const float4 v = reinterpret_cast<const float4*>(xin)[t];
    float u0 = v.x + v.y + v.z + v.w;
    float u1r = v.x - v.z;
    float u1i = v.w - v.y;
    float u2 = v.x - v.y + v.z - v.w;
    uint32_t* dst = reinterpret_cast<uint32_t*>(g_U) + (size_t)b * 4096 + x;
    dst[0]    = tf32r(u0);
    dst[1024] = tf32r(u1r);
    dst[2048] = tf32r(u1i);
    dst[3072] = tf32r(u2);
}

// ---------------------------------------------------------------------------
// transform_e: one thread per (y, x)
// ---------------------------------------------------------------------------
__global__ void transform_e_kernel(const float* __restrict__ eig) {
    int t = blockIdx.x * blockDim.x + threadIdx.x;   // 1024*1024
    if (t >= GY * GX) return;
    const float4 e = reinterpret_cast<const float4*>(eig)[t];
    float f0 = (e.x + e.y + e.z + e.w) * 0.25f;
    float f2 = (e.x - e.y + e.z - e.w) * 0.25f;
    float er = (e.x - e.z) * 0.5f;
    float ei = (e.w - e.y) * 0.5f;
    uint32_t* dst = reinterpret_cast<uint32_t*>(g_E) + t;
    const size_t P = (size_t)GY * GX;
    dst[0]     = tf32r(f0);
    dst[P]     = tf32r(f2);
    dst[2 * P] = tf32r(er);
    dst[3 * P] = tf32r(ei);
    dst[4 * P] = tf32r(-ei);
}

// ---------------------------------------------------------------------------
// GEMM: CTA tile 128 (b) x 32 (gy), K over gx in 32-chunks.
// 8 warps (4 m x 2 n), warp tile 32m x 16gy. 4 accumulator sets.
// ---------------------------------------------------------------------------
#define BM 128
#define BGY 32
#define BK 32
#define LDSW 36
#define A_ST (4 * 128 * LDSW)          // 18432 floats
#define E_ST (5 * 32 * LDSW)           // 5760 floats
#define STAGE_F (A_ST + E_ST)          // 24192 floats
#define SMEM_BYTES (2 * STAGE_F * 4)   // 193536 bytes

__global__ void __launch_bounds__(256, 1) gemm_freq_kernel(float* __restrict__ out) {
    extern __shared__ float smem[];

    const int tid = threadIdx.x;
    const int bgy0 = blockIdx.x * BGY;   // gy tile base
    const int bm0  = blockIdx.y * BM;    // b tile base

    const int warp  = tid >> 5;
    const int lane  = tid & 31;
    const int g     = lane >> 2;
    const int tg    = lane & 3;
    const int warpM = warp & 3;
    const int warpN = warp >> 2;
    const int m0    = warpM * 32;
    const int n0    = warpN * 16;

    // acc[set][mi][ni][4]: set 0=F0, 1=F2, 2=F1r, 3=F1i
    float acc[4][2][2][4];
    #pragma unroll
    for (int s = 0; s < 4; s++)
        #pragma unroll
        for (int mi = 0; mi < 2; mi++)
            #pragma unroll
            for (int ni = 0; ni < 2; ni++)
                #pragma unroll
                for (int q = 0; q < 4; q++) acc[s][mi][ni][q] = 0.0f;

    auto load_tile = [&](int kk, int buf) {
        float* baseA = smem + buf * STAGE_F;
        float* baseE = baseA + A_ST;
        // A: 4 comps x 128 rows x 8 chunks = 4096 ops
        #pragma unroll
        for (int j = 0; j < 16; j++) {
            int l = tid + j * 256;
            int comp = l >> 10;
            int rem  = l & 1023;
            int row  = rem >> 3;
            int c4   = rem & 7;
            const float* src = g_U + (size_t)(bm0 + row) * 4096 + comp * 1024 + kk + c4 * 4;
            uint32_t dst = (uint32_t)__cvta_generic_to_shared(
                baseA + (comp * 128 + row) * LDSW + c4 * 4);
            asm volatile("cp.async.cg.shared.global [%0], [%1], 16;\n"
                         :: "r"(dst), "l"(src) : "memory");
        }
        // E: 5 planes x 32 rows x 8 chunks = 1280 ops
        #pragma unroll
        for (int j = 0; j < 5; j++) {
            int l = tid + j * 256;
            int p    = l >> 8;
            int rem  = l & 255;
            int row  = rem >> 3;
            int c4   = rem & 7;
            const float* src = g_E + (size_t)p * (GY * GX) + (size_t)(bgy0 + row) * GX + kk + c4 * 4;
            uint32_t dst = (uint32_t)__cvta_generic_to_shared(
                baseE + (p * 32 + row) * LDSW + c4 * 4);
            asm volatile("cp.async.cg.shared.global [%0], [%1], 16;\n"
                         :: "r"(dst), "l"(src) : "memory");
        }
        asm volatile("cp.async.commit_group;\n" ::: "memory");
    };

    const int NK = GX / BK;   // 32
    load_tile(0, 0);

    for (int kt = 0; kt < NK; kt++) {
        if (kt + 1 < NK) {
            load_tile((kt + 1) * BK, (kt + 1) & 1);
            asm volatile("cp.async.wait_group 1;\n" ::: "memory");
        } else {
            asm volatile("cp.async.wait_group 0;\n" ::: "memory");
        }
        __syncthreads();

        const float* baseA = smem + (kt & 1) * STAGE_F;
        const uint32_t* Asu = reinterpret_cast<const uint32_t*>(baseA);
        const uint32_t* Esu = reinterpret_cast<const uint32_t*>(baseA + A_ST);

        #pragma unroll
        for (int ks = 0; ks < 4; ks++) {
            const int kb = ks * 8;
            // A fragments: 4 comps (0=u0,1=u1r,2=u1i,3=u2)
            uint32_t uf[4][2][4];
            #pragma unroll
            for (int c = 0; c < 4; c++) {
                #pragma unroll
                for (int mi = 0; mi < 2; mi++) {
                    int rbase = (c * 128 + m0 + mi * 16 + g) * LDSW + kb + tg;
                    uf[c][mi][0] = Asu[rbase];
                    uf[c][mi][1] = Asu[rbase + 8 * LDSW];
                    uf[c][mi][2] = Asu[rbase + 4];
                    uf[c][mi][3] = Asu[rbase + 8 * LDSW + 4];
                }
            }
            // E fragments: 5 planes (0=P0,1=P2,2=P1r,3=P1i,4=P1n)
            uint32_t ef[5][2][2];
            #pragma unroll
            for (int p = 0; p < 5; p++) {
                #pragma unroll
                for (int ni = 0; ni < 2; ni++) {
                    int rb = (p * 32 + n0 + ni * 8 + g) * LDSW + kb + tg;
                    ef[p][ni][0] = Esu[rb];
                    ef[p][ni][1] = Esu[rb + 4];
                }
            }

            #define MMA(ACC, AF, BF)                                              \
                asm volatile(                                                     \
                    "mma.sync.aligned.m16n8k8.row.col.f32.tf32.tf32.f32 "         \
                    "{%0,%1,%2,%3}, {%4,%5,%6,%7}, {%8,%9}, {%0,%1,%2,%3};\n"     \
                    : "+f"((ACC)[0]), "+f"((ACC)[1]), "+f"((ACC)[2]), "+f"((ACC)[3]) \
                    : "r"((AF)[0]), "r"((AF)[1]), "r"((AF)[2]), "r"((AF)[3]),     \
                      "r"((BF)[0]), "r"((BF)[1]))

            #pragma unroll
            for (int mi = 0; mi < 2; mi++) {
                #pragma unroll
                for (int ni = 0; ni < 2; ni++) {
                    MMA(acc[0][mi][ni], uf[0][mi], ef[0][ni]);   // F0  += P0  * u0
                    MMA(acc[1][mi][ni], uf[3][mi], ef[1][ni]);   // F2  += P2  * u2
                    MMA(acc[2][mi][ni], uf[1][mi], ef[2][ni]);   // F1r += P1r * u1r
                    MMA(acc[2][mi][ni], uf[2][mi], ef[4][ni]);   // F1r += P1n * u1i
                    MMA(acc[3][mi][ni], uf[1][mi], ef[3][ni]);   // F1i += P1i * u1r
                    MMA(acc[3][mi][ni], uf[2][mi], ef[2][ni]);   // F1i += P1r * u1i
                }
            }
            #undef MMA
        }
        __syncthreads();
    }

    // Epilogue: inverse-DFT butterfly, float4 store per element.
    #pragma unroll
    for (int mi = 0; mi < 2; mi++) {
        #pragma unroll
        for (int ni = 0; ni < 2; ni++) {
            #pragma unroll
            for (int q = 0; q < 2; q++) {
                #pragma unroll
                for (int h = 0; h < 2; h++) {   // h=0: row g (d0,d1); h=1: row g+8 (d2,d3)
                    int row = bm0 + m0 + mi * 16 + g + h * 8;
                    int gy  = bgy0 + n0 + ni * 8 + 2 * tg + q;
                    float F0  = acc[0][mi][ni][2 * h + q];
                    float F2  = acc[1][mi][ni][2 * h + q];
                    float F1r = acc[2][mi][ni][2 * h + q];
                    float F1i = acc[3][mi][ni][2 * h + q];
                    float4 o;
                    o.x = F0 + F1r + F2;
                    o.y = F0 - F1i - F2;
                    o.z = F0 - F1r + F2;
                    o.w = F0 + F1i - F2;
                    *reinterpret_cast<float4*>(out + (size_t)row * N_DIM + 4 * gy) = o;
                }
            }
        }
    }
}

// ---------------------------------------------------------------------------
extern "C" void kernel_launch(void* const* d_in, const int* in_sizes, int n_in,
                              void* d_out, int out_size) {
    const float* x   = (const float*)d_in[0];   // (4096, 4096) f32
    const float* eig = (const float*)d_in[1];   // (1024, 1024, 4) f32
    float* out       = (float*)d_out;           // (4096, 4096) f32

    cudaFuncSetAttribute(gemm_freq_kernel,
                         cudaFuncAttributeMaxDynamicSharedMemorySize, SMEM_BYTES);

    transform_x_kernel<<<(B_DIM * GX + 255) / 256, 256>>>(x);
    transform_e_kernel<<<(GY * GX + 255) / 256, 256>>>(eig);

    dim3 grid(GY / BGY, B_DIM / BM);   // (32, 32)
    gemm_freq_kernel<<<grid, 256, SMEM_BYTES>>>(out);
    (void)in_sizes; (void)n_in; (void)out_size;
}

// round 5
// speedup vs baseline: 2.5214x; 1.4486x over previous
#include <cuda_runtime.h>
#include <cstdint>

// Block-circulant linear via length-4 DFT diagonalization (6/16 dense work),
// with MMA-fragment-order scratch layouts so every fragment load is one wide LDS.
//
//   u0=a+b+c+d, u1r=a-c, u1i=d-b, u2=a-b+c-d  (per x block of x)
//   P0=Fe0/4, P2=Fe2/4, P1r=(e0-e2)/2, P1i=(e3-e1)/2, P1n=-P1i
//   F0=sum P0*u0 ; F2=sum P2*u2
//   F1r=sum P1r*u1r + P1n*u1i ; F1i=sum P1i*u1r + P1r*u1i
//   o0=F0+F1r+F2  o1=F0-F1i-F2  o2=F0-F1r+F2  o3=F0+F1i-F2

#define B_DIM 4096
#define GX 1024
#define GY 1024
#define N_DIM 4096

// g_U: [bmt(32)][kt(32)][c(4)][mt(8)][ks(4)][lane(32)][4]  (64KB tiles)
// g_E: [yt(16)][kt(32)][p(5)][nt(8)][ks(4)][lane(32)][2]   (40KB tiles)
#define A_TILE_F 16384
#define E_TILE_F 10240
__device__ float g_U[(size_t)32 * 32 * A_TILE_F];   // 64 MB
__device__ float g_E[(size_t)16 * 32 * E_TILE_F];   // 20 MB

__device__ __forceinline__ uint32_t tf32r(float f) {
    uint32_t u;
    asm("cvt.rna.tf32.f32 %0, %1;" : "=r"(u) : "f"(f));
    return u;
}

// ---------------------------------------------------------------------------
// transform_x: one thread per (b, xblk); writes 4 comps in fragment order.
// ---------------------------------------------------------------------------
__global__ void transform_x_kernel(const float* __restrict__ xin) {
    int t = blockIdx.x * blockDim.x + threadIdx.x;   // 4096*1024
    if (t >= B_DIM * GX) return;
    int b = t >> 10;
    int x = t & 1023;
    const float4 v = reinterpret_cast<const float4*>(xin)[t];
    float u[4];
    u[0] = v.x + v.y + v.z + v.w;
    u[1] = v.x - v.z;
    u[2] = v.w - v.y;
    u[3] = v.x - v.y + v.z - v.w;

    int bmt = b >> 7, mt = (b >> 4) & 7, row16 = b & 15;
    int kt = x >> 5, ks = (x >> 3) & 3, kc = x & 7;
    int lane = (row16 & 7) * 4 + (kc & 3);
    int idx  = (row16 >> 3) + 2 * (kc >> 2);
    uint32_t* tile = reinterpret_cast<uint32_t*>(g_U) + (size_t)(bmt * 32 + kt) * A_TILE_F;
    #pragma unroll
    for (int c = 0; c < 4; c++)
        tile[((c * 8 + mt) * 4 + ks) * 128 + lane * 4 + idx] = tf32r(u[c]);
}

// ---------------------------------------------------------------------------
// transform_e: one thread per (y, x); writes 5 planes in fragment order.
// ---------------------------------------------------------------------------
__global__ void transform_e_kernel(const float* __restrict__ eig) {
    int t = blockIdx.x * blockDim.x + threadIdx.x;   // 1024*1024
    if (t >= GY * GX) return;
    int y = t >> 10;
    int x = t & 1023;
    const float4 e = reinterpret_cast<const float4*>(eig)[t];
    float p[5];
    p[0] = (e.x + e.y + e.z + e.w) * 0.25f;   // P0
    p[1] = (e.x - e.y + e.z - e.w) * 0.25f;   // P2
    p[2] = (e.x - e.z) * 0.5f;                // P1r
    p[3] = (e.w - e.y) * 0.5f;                // P1i
    p[4] = -p[3];                             // P1n

    int yt = y >> 6, nt = (y >> 3) & 7, g = y & 7;
    int kt = x >> 5, ks = (x >> 3) & 3, kc = x & 7;
    int lane = g * 4 + (kc & 3);
    int idx  = kc >> 2;
    uint32_t* tile = reinterpret_cast<uint32_t*>(g_E) + (size_t)(yt * 32 + kt) * E_TILE_F;
    #pragma unroll
    for (int q = 0; q < 5; q++)
        tile[((q * 8 + nt) * 4 + ks) * 64 + lane * 2 + idx] = tf32r(p[q]);
}

// ---------------------------------------------------------------------------
// GEMM: CTA out-tile 128(b) x 64(gy) blocks, K over gx in 32-chunks.
// 8 warps (4m x 2n), warp tile 32m x 32gy. 4 accumulator sets.
// ---------------------------------------------------------------------------
#define STAGE_F (A_TILE_F + E_TILE_F)       // 26624 floats
#define SMEM_BYTES (2 * STAGE_F * 4)        // 212992 bytes

__global__ void __launch_bounds__(256, 1) gemm_freq_kernel(float* __restrict__ out) {
    extern __shared__ float smem[];

    const int tid  = threadIdx.x;
    const int yt   = blockIdx.x;            // gy tile (64 blocks)
    const int bmt  = blockIdx.y;            // b tile (128 rows)
    const int bgy0 = yt * 64;
    const int bm0  = bmt * 128;

    const int warp  = tid >> 5;
    const int lane  = tid & 31;
    const int g     = lane >> 2;
    const int tg    = lane & 3;
    const int warpM = warp & 3;             // 0..3 -> m0 = warpM*32
    const int warpN = warp >> 2;            // 0..1 -> n0 = warpN*32

    float acc[4][2][4][4];                  // [set][mi][ni][frag]
    #pragma unroll
    for (int s = 0; s < 4; s++)
        #pragma unroll
        for (int mi = 0; mi < 2; mi++)
            #pragma unroll
            for (int ni = 0; ni < 4; ni++)
                #pragma unroll
                for (int q = 0; q < 4; q++) acc[s][mi][ni][q] = 0.0f;

    const float* gA = g_U + (size_t)bmt * 32 * A_TILE_F;
    const float* gE = g_E + (size_t)yt * 32 * E_TILE_F;

    auto load_tile = [&](int kt, int buf) {
        float* baseA = smem + buf * STAGE_F;
        float* baseE = baseA + A_TILE_F;
        const float* sA = gA + (size_t)kt * A_TILE_F;
        const float* sE = gE + (size_t)kt * E_TILE_F;
        #pragma unroll
        for (int j = 0; j < 16; j++) {
            int ck = tid + j * 256;
            uint32_t dst = (uint32_t)__cvta_generic_to_shared(baseA + ck * 4);
            asm volatile("cp.async.cg.shared.global [%0], [%1], 16;\n"
                         :: "r"(dst), "l"(sA + ck * 4) : "memory");
        }
        #pragma unroll
        for (int j = 0; j < 10; j++) {
            int ck = tid + j * 256;
            uint32_t dst = (uint32_t)__cvta_generic_to_shared(baseE + ck * 4);
            asm volatile("cp.async.cg.shared.global [%0], [%1], 16;\n"
                         :: "r"(dst), "l"(sE + ck * 4) : "memory");
        }
        asm volatile("cp.async.commit_group;\n" ::: "memory");
    };

    const int NK = 32;
    load_tile(0, 0);

    #define MMA(ACC, AF, B0, B1)                                                  \
        asm volatile(                                                             \
            "mma.sync.aligned.m16n8k8.row.col.f32.tf32.tf32.f32 "                 \
            "{%0,%1,%2,%3}, {%4,%5,%6,%7}, {%8,%9}, {%0,%1,%2,%3};\n"             \
            : "+f"((ACC)[0]), "+f"((ACC)[1]), "+f"((ACC)[2]), "+f"((ACC)[3])      \
            : "r"((AF).x), "r"((AF).y), "r"((AF).z), "r"((AF).w),                 \
              "r"(B0), "r"(B1))

    for (int kt = 0; kt < NK; kt++) {
        if (kt + 1 < NK) {
            load_tile(kt + 1, (kt + 1) & 1);
            asm volatile("cp.async.wait_group 1;\n" ::: "memory");
        } else {
            asm volatile("cp.async.wait_group 0;\n" ::: "memory");
        }
        __syncthreads();

        const float* baseA = smem + (kt & 1) * STAGE_F;
        const uint4* A4 = reinterpret_cast<const uint4*>(baseA);
        const uint2* E2 = reinterpret_cast<const uint2*>(baseA + A_TILE_F);

        #pragma unroll
        for (int ks = 0; ks < 4; ks++) {
            uint4 uf[4][2];
            #pragma unroll
            for (int c = 0; c < 4; c++)
                #pragma unroll
                for (int mi = 0; mi < 2; mi++)
                    uf[c][mi] = A4[((c * 8 + warpM * 2 + mi) * 4 + ks) * 32 + lane];

            #pragma unroll
            for (int ni = 0; ni < 4; ni++) {
                uint2 ef[5];
                #pragma unroll
                for (int p = 0; p < 5; p++)
                    ef[p] = E2[((p * 8 + warpN * 4 + ni) * 4 + ks) * 32 + lane];

                #pragma unroll
                for (int mi = 0; mi < 2; mi++) {
                    MMA(acc[0][mi][ni], uf[0][mi], ef[0].x, ef[0].y);  // F0  += P0 *u0
                    MMA(acc[1][mi][ni], uf[3][mi], ef[1].x, ef[1].y);  // F2  += P2 *u2
                    MMA(acc[2][mi][ni], uf[1][mi], ef[2].x, ef[2].y);  // F1r += P1r*u1r
                    MMA(acc[2][mi][ni], uf[2][mi], ef[4].x, ef[4].y);  // F1r += P1n*u1i
                    MMA(acc[3][mi][ni], uf[1][mi], ef[3].x, ef[3].y);  // F1i += P1i*u1r
                    MMA(acc[3][mi][ni], uf[2][mi], ef[2].x, ef[2].y);  // F1i += P1r*u1i
                }
            }
        }
        __syncthreads();
    }
    #undef MMA

    // Epilogue: inverse-DFT butterfly, one float4 per output block element.
    #pragma unroll
    for (int mi = 0; mi < 2; mi++) {
        #pragma unroll
        for (int ni = 0; ni < 4; ni++) {
            #pragma unroll
            for (int h = 0; h < 2; h++) {
                #pragma unroll
                for (int q = 0; q < 2; q++) {
                    int row = bm0 + warpM * 32 + mi * 16 + g + h * 8;
                    int gy  = bgy0 + warpN * 32 + ni * 8 + 2 * tg + q;
                    float F0  = acc[0][mi][ni][2 * h + q];
                    float F2  = acc[1][mi][ni][2 * h + q];
                    float F1r = acc[2][mi][ni][2 * h + q];
                    float F1i = acc[3][mi][ni][2 * h + q];
                    float4 o;
                    o.x = F0 + F1r + F2;
                    o.y = F0 - F1i - F2;
                    o.z = F0 - F1r + F2;
                    o.w = F0 + F1i - F2;
                    *reinterpret_cast<float4*>(out + (size_t)row * N_DIM + 4 * gy) = o;
                }
            }
        }
    }
}

// ---------------------------------------------------------------------------
extern "C" void kernel_launch(void* const* d_in, const int* in_sizes, int n_in,
                              void* d_out, int out_size) {
    const float* x   = (const float*)d_in[0];   // (4096, 4096) f32
    const float* eig = (const float*)d_in[1];   // (1024, 1024, 4) f32
    float* out       = (float*)d_out;           // (4096, 4096) f32

    cudaFuncSetAttribute(gemm_freq_kernel,
                         cudaFuncAttributeMaxDynamicSharedMemorySize, SMEM_BYTES);

    transform_x_kernel<<<(B_DIM * GX + 255) / 256, 256>>>(x);
    transform_e_kernel<<<(GY * GX + 255) / 256, 256>>>(eig);

    dim3 grid(GY / 64, B_DIM / 128);   // (16, 32) = 512 CTAs
    gemm_freq_kernel<<<grid, 256, SMEM_BYTES>>>(out);
    (void)in_sizes; (void)n_in; (void)out_size;
}

// round 6
// speedup vs baseline: 4.3640x; 1.7308x over previous
#include <cuda_runtime.h>
#include <cuda_fp16.h>
#include <cstdint>

// Block-circulant linear via length-4 DFT diagonalization (6/16 dense work),
// fp16 operands (same 10-bit mantissa as tf32), f32 accumulation,
// MMA-fragment-order scratch so every fragment load is one wide LDS.
//
//   u0=a+b+c+d, u1r=a-c, u1i=d-b, u2=a-b+c-d  (per x block of x)
//   P0=Fe0/4, P2=Fe2/4, P1r=(e0-e2)/2, P1i=(e3-e1)/2, P1n=-P1i
//   F0=sum P0*u0 ; F2=sum P2*u2
//   F1r=sum P1r*u1r + P1n*u1i ; F1i=sum P1i*u1r + P1r*u1i
//   o0=F0+F1r+F2  o1=F0-F1i-F2  o2=F0-F1r+F2  o3=F0+F1i-F2

#define B_DIM 4096
#define GX 1024
#define GY 1024
#define N_DIM 4096

// A tile (per bmt,kt): [c(4)][mt(8)][kstep(2)][lane(32)][reg(4)] f16x2 = 32KB
// E tile (per yt, kt): [p(5)][nt(8)][kstep(2)][lane(32)][reg(2)] f16x2 = 20KB
#define A_TILE_U32 8192
#define E_TILE_U32 5120
__device__ uint32_t g_U[(size_t)32 * 32 * A_TILE_U32];   // 32 MB
__device__ uint32_t g_E[(size_t)16 * 32 * E_TILE_U32];   // 10 MB

__device__ __forceinline__ uint32_t pack_h2(float lo, float hi) {
    __half2 h = __floats2half2_rn(lo, hi);   // x=lo (bits 0-15), y=hi
    return *reinterpret_cast<uint32_t*>(&h);
}

// ---------------------------------------------------------------------------
// transform_x: thread = (bmt, kt, mt, lane); produces the exact fp16 A frags.
// ---------------------------------------------------------------------------
__global__ void __launch_bounds__(256) transform_x_kernel(const float* __restrict__ xin) {
    int t = blockIdx.x * blockDim.x + threadIdx.x;   // 262144
    int lane = t & 31;
    int mt   = (t >> 5) & 7;
    int kt   = (t >> 8) & 31;
    int bmt  = t >> 13;
    int g = lane >> 2, tg = lane & 3;

    uint32_t regs[4][2][4];   // [c][kstep][reg]
    #pragma unroll
    for (int hi = 0; hi < 2; hi++) {
        int b = bmt * 128 + mt * 16 + g + 8 * hi;
        const float4* xr = reinterpret_cast<const float4*>(xin) + (size_t)b * GX;
        #pragma unroll
        for (int kstep = 0; kstep < 2; kstep++) {
            #pragma unroll
            for (int khi = 0; khi < 2; khi++) {
                int xb = kt * 32 + kstep * 16 + khi * 8 + 2 * tg;
                float4 f0 = xr[xb];
                float4 f1 = xr[xb + 1];
                float ue[4], uo[4];
                ue[0] = f0.x + f0.y + f0.z + f0.w;  uo[0] = f1.x + f1.y + f1.z + f1.w;
                ue[1] = f0.x - f0.z;                uo[1] = f1.x - f1.z;
                ue[2] = f0.w - f0.y;                uo[2] = f1.w - f1.y;
                ue[3] = f0.x - f0.y + f0.z - f0.w;  uo[3] = f1.x - f1.y + f1.z - f1.w;
                int r = hi + 2 * khi;
                #pragma unroll
                for (int c = 0; c < 4; c++) regs[c][kstep][r] = pack_h2(ue[c], uo[c]);
            }
        }
    }
    uint32_t* tile = g_U + (size_t)(bmt * 32 + kt) * A_TILE_U32;
    #pragma unroll
    for (int c = 0; c < 4; c++)
        #pragma unroll
        for (int kstep = 0; kstep < 2; kstep++) {
            int idx = (((c * 8 + mt) * 2 + kstep) * 32 + lane) * 4;
            *reinterpret_cast<uint4*>(tile + idx) =
                make_uint4(regs[c][kstep][0], regs[c][kstep][1],
                           regs[c][kstep][2], regs[c][kstep][3]);
        }
}

// ---------------------------------------------------------------------------
// transform_e: thread = (yt, kt, nt, lane); produces the exact fp16 B frags.
// ---------------------------------------------------------------------------
__global__ void __launch_bounds__(256) transform_e_kernel(const float* __restrict__ eig) {
    int t = blockIdx.x * blockDim.x + threadIdx.x;   // 131072
    int lane = t & 31;
    int nt   = (t >> 5) & 7;
    int kt   = (t >> 8) & 31;
    int yt   = t >> 13;
    int g = lane >> 2, tg = lane & 3;

    int y = yt * 64 + nt * 8 + g;
    const float4* er = reinterpret_cast<const float4*>(eig) + (size_t)y * GX;

    uint32_t regs[5][2][2];   // [p][kstep][reg=khi]
    #pragma unroll
    for (int kstep = 0; kstep < 2; kstep++) {
        #pragma unroll
        for (int khi = 0; khi < 2; khi++) {
            int xb = kt * 32 + kstep * 16 + khi * 8 + 2 * tg;
            float4 e0 = er[xb];
            float4 e1 = er[xb + 1];
            float pe[5], po[5];
            pe[0] = (e0.x + e0.y + e0.z + e0.w) * 0.25f;
            po[0] = (e1.x + e1.y + e1.z + e1.w) * 0.25f;
            pe[1] = (e0.x - e0.y + e0.z - e0.w) * 0.25f;
            po[1] = (e1.x - e1.y + e1.z - e1.w) * 0.25f;
            pe[2] = (e0.x - e0.z) * 0.5f;   po[2] = (e1.x - e1.z) * 0.5f;
            pe[3] = (e0.w - e0.y) * 0.5f;   po[3] = (e1.w - e1.y) * 0.5f;
            pe[4] = -pe[3];                 po[4] = -po[3];
            #pragma unroll
            for (int p = 0; p < 5; p++) regs[p][kstep][khi] = pack_h2(pe[p], po[p]);
        }
    }
    uint32_t* tile = g_E + (size_t)(yt * 32 + kt) * E_TILE_U32;
    #pragma unroll
    for (int p = 0; p < 5; p++)
        #pragma unroll
        for (int kstep = 0; kstep < 2; kstep++) {
            int idx = (((p * 8 + nt) * 2 + kstep) * 32 + lane) * 2;
            *reinterpret_cast<uint2*>(tile + idx) =
                make_uint2(regs[p][kstep][0], regs[p][kstep][1]);
        }
}

// ---------------------------------------------------------------------------
// GEMM: CTA 128(b) x 64(gy blocks), 8 warps (4m x 2n), warp 32m x 32gy.
// fp16 m16n8k16 MMA, 3-stage cp.async pipeline, one barrier per kt.
// ---------------------------------------------------------------------------
#define STAGE_U32 (A_TILE_U32 + E_TILE_U32)       // 13312 (52KB)
#define STAGES 3
#define SMEM_BYTES (STAGES * STAGE_U32 * 4)       // 159744

__global__ void __launch_bounds__(256, 1) gemm_freq_kernel(float* __restrict__ out) {
    extern __shared__ uint32_t smem[];

    const int tid  = threadIdx.x;
    const int yt   = blockIdx.x;
    const int bmt  = blockIdx.y;
    const int bgy0 = yt * 64;
    const int bm0  = bmt * 128;

    const int warp  = tid >> 5;
    const int lane  = tid & 31;
    const int g     = lane >> 2;
    const int tg    = lane & 3;
    const int warpM = warp & 3;
    const int warpN = warp >> 2;

    float acc[4][2][4][4];   // [set][mi][ni][frag]  set: 0=F0 1=F2 2=F1r 3=F1i
    #pragma unroll
    for (int s = 0; s < 4; s++)
        #pragma unroll
        for (int mi = 0; mi < 2; mi++)
            #pragma unroll
            for (int ni = 0; ni < 4; ni++)
                #pragma unroll
                for (int q = 0; q < 4; q++) acc[s][mi][ni][q] = 0.0f;

    const uint32_t* gA = g_U + (size_t)bmt * 32 * A_TILE_U32;
    const uint32_t* gE = g_E + (size_t)yt * 32 * E_TILE_U32;

    auto load_tile = [&](int kt, int buf) {
        uint32_t* baseA = smem + buf * STAGE_U32;
        uint32_t* baseE = baseA + A_TILE_U32;
        const uint32_t* sA = gA + (size_t)kt * A_TILE_U32;
        const uint32_t* sE = gE + (size_t)kt * E_TILE_U32;
        #pragma unroll
        for (int j = 0; j < 8; j++) {
            int ck = tid + j * 256;
            uint32_t dst = (uint32_t)__cvta_generic_to_shared(baseA + ck * 4);
            asm volatile("cp.async.cg.shared.global [%0], [%1], 16;\n"
                         :: "r"(dst), "l"(sA + ck * 4) : "memory");
        }
        #pragma unroll
        for (int j = 0; j < 5; j++) {
            int ck = tid + j * 256;
            uint32_t dst = (uint32_t)__cvta_generic_to_shared(baseE + ck * 4);
            asm volatile("cp.async.cg.shared.global [%0], [%1], 16;\n"
                         :: "r"(dst), "l"(sE + ck * 4) : "memory");
        }
        asm volatile("cp.async.commit_group;\n" ::: "memory");
    };

    const int NK = 32;
    load_tile(0, 0);
    load_tile(1, 1);

    #define MMA(ACC, AF, B0, B1)                                                  \
        asm volatile(                                                             \
            "mma.sync.aligned.m16n8k16.row.col.f32.f16.f16.f32 "                  \
            "{%0,%1,%2,%3}, {%4,%5,%6,%7}, {%8,%9}, {%0,%1,%2,%3};\n"             \
            : "+f"((ACC)[0]), "+f"((ACC)[1]), "+f"((ACC)[2]), "+f"((ACC)[3])      \
            : "r"((AF).x), "r"((AF).y), "r"((AF).z), "r"((AF).w),                 \
              "r"(B0), "r"(B1))

    for (int kt = 0; kt < NK; kt++) {
        if (kt + 1 < NK) {
            asm volatile("cp.async.wait_group 1;\n" ::: "memory");
        } else {
            asm volatile("cp.async.wait_group 0;\n" ::: "memory");
        }
        __syncthreads();
        if (kt + 2 < NK) load_tile(kt + 2, (kt + 2) % STAGES);

        const uint32_t* base = smem + (kt % STAGES) * STAGE_U32;
        const uint4* A4 = reinterpret_cast<const uint4*>(base);
        const uint2* E2 = reinterpret_cast<const uint2*>(base + A_TILE_U32);

        #pragma unroll
        for (int kstep = 0; kstep < 2; kstep++) {
            uint4 uf[4][2];
            #pragma unroll
            for (int c = 0; c < 4; c++)
                #pragma unroll
                for (int mi = 0; mi < 2; mi++)
                    uf[c][mi] = A4[((c * 8 + warpM * 2 + mi) * 2 + kstep) * 32 + lane];

            #pragma unroll
            for (int ni = 0; ni < 4; ni++) {
                uint2 ef[5];
                #pragma unroll
                for (int p = 0; p < 5; p++)
                    ef[p] = E2[((p * 8 + warpN * 4 + ni) * 2 + kstep) * 32 + lane];

                #pragma unroll
                for (int mi = 0; mi < 2; mi++) {
                    MMA(acc[0][mi][ni], uf[0][mi], ef[0].x, ef[0].y);  // F0  += P0 *u0
                    MMA(acc[1][mi][ni], uf[3][mi], ef[1].x, ef[1].y);  // F2  += P2 *u2
                    MMA(acc[2][mi][ni], uf[1][mi], ef[2].x, ef[2].y);  // F1r += P1r*u1r
                    MMA(acc[2][mi][ni], uf[2][mi], ef[4].x, ef[4].y);  // F1r += P1n*u1i
                    MMA(acc[3][mi][ni], uf[1][mi], ef[3].x, ef[3].y);  // F1i += P1i*u1r
                    MMA(acc[3][mi][ni], uf[2][mi], ef[2].x, ef[2].y);  // F1i += P1r*u1i
                }
            }
        }
    }
    #undef MMA

    // Epilogue: inverse-DFT butterfly, one float4 per output block element.
    #pragma unroll
    for (int mi = 0; mi < 2; mi++) {
        #pragma unroll
        for (int ni = 0; ni < 4; ni++) {
            #pragma unroll
            for (int h = 0; h < 2; h++) {
                #pragma unroll
                for (int q = 0; q < 2; q++) {
                    int row = bm0 + warpM * 32 + mi * 16 + g + h * 8;
                    int gy  = bgy0 + warpN * 32 + ni * 8 + 2 * tg + q;
                    float F0  = acc[0][mi][ni][2 * h + q];
                    float F2  = acc[1][mi][ni][2 * h + q];
                    float F1r = acc[2][mi][ni][2 * h + q];
                    float F1i = acc[3][mi][ni][2 * h + q];
                    float4 o;
                    o.x = F0 + F1r + F2;
                    o.y = F0 - F1i - F2;
                    o.z = F0 - F1r + F2;
                    o.w = F0 + F1i - F2;
                    *reinterpret_cast<float4*>(out + (size_t)row * N_DIM + 4 * gy) = o;
                }
            }
        }
    }
}

// ---------------------------------------------------------------------------
extern "C" void kernel_launch(void* const* d_in, const int* in_sizes, int n_in,
                              void* d_out, int out_size) {
    const float* x   = (const float*)d_in[0];   // (4096, 4096) f32
    const float* eig = (const float*)d_in[1];   // (1024, 1024, 4) f32
    float* out       = (float*)d_out;           // (4096, 4096) f32

    cudaFuncSetAttribute(gemm_freq_kernel,
                         cudaFuncAttributeMaxDynamicSharedMemorySize, SMEM_BYTES);

    transform_x_kernel<<<262144 / 256, 256>>>(x);
    transform_e_kernel<<<131072 / 256, 256>>>(eig);

    dim3 grid(GY / 64, B_DIM / 128);   // (16, 32) = 512 CTAs
    gemm_freq_kernel<<<grid, 256, SMEM_BYTES>>>(out);
    (void)in_sizes; (void)n_in; (void)out_size;
}